// round 11
// baseline (speedup 1.0000x reference)
#include <cuda_runtime.h>
#include <cstdint>

// InteractionArch via single-pass tf32 mma.sync (m16n8k8), exploiting Gram
// symmetry: the PTX B-fragment register layout for .row.col equals the
// A-fragment layout when both come from the same matrix, so B needs NO loads
// (b0=a0, b1=a2; +8-row n-tile uses a1,a3). 8 LDS.32 + 6 MMA per k8-step.
//
// Accuracy: inputs rounded once with cvt.rna.tf32 (eps ~ 2^-11); norm-based
// rel_err model (calibrated on the bf16x3 rounds: predicted 3.8e-6 vs
// measured 4.46e-6) gives ~4e-4 here, inside the 1e-3 threshold with margin.
//
// Structure = round-10 pipeline: 4 K-stages of 32, double-buffered smem
// (2 x 16 KB fp32/tf32), register prefetch of stage s+1 issued right after
// the barrier and consumed at the next STS, so LDG latency hides under MMAs.
//
// Swizzle (128 B fp32 rows, 8 x 16 B chunks): chunk c4 of row r at position
// c4 ^ (r & 7). Fragment LDS.32 (rows lane>>2 spanning 8, elem lane&3) maps
// to 32 distinct banks; STS.128 octet phases hit 8 distinct granules.

#define FEAT 27
#define KDIM 128
#define NPAIR 351
#define GROUP 4
#define THREADS 128
#define BUF_BYTES 16384        // one stage: 4 groups x 32 rows x 128 B
#define GRP_BYTES 4096         // 32 rows x 128 B
#define STG_STRIDE 29
#define STG_WARP 783           // 27 * 29 floats

__device__ __forceinline__ uint32_t to_tf32(float x) {
    uint32_t u;
    asm("cvt.rna.tf32.f32 %0, %1;" : "=r"(u) : "f"(x));
    return u;
}

__device__ __forceinline__ void mma_tf32(float* c, const uint32_t* a,
                                         uint32_t b0, uint32_t b1) {
    asm volatile(
        "mma.sync.aligned.m16n8k8.row.col.f32.tf32.tf32.f32 "
        "{%0,%1,%2,%3}, {%4,%5,%6,%7}, {%8,%9}, {%0,%1,%2,%3};"
        : "+f"(c[0]), "+f"(c[1]), "+f"(c[2]), "+f"(c[3])
        : "r"(a[0]), "r"(a[1]), "r"(a[2]), "r"(a[3]), "r"(b0), "r"(b1));
}

__global__ __launch_bounds__(THREADS)
void interaction_kernel(const float* __restrict__ dense,
                        const float* __restrict__ sparse,
                        float* __restrict__ out,
                        int B)
{
    __shared__ __align__(1024) char smem[2 * BUF_BYTES];   // 32 KB

    const int tid = threadIdx.x;
    const int wid = tid >> 5;
    const int lane = tid & 31;
    const long bbase = (long)blockIdx.x * GROUP;

    // ---- load mapping: quarter-warp per feature-row line (coalesced) ----
    const int lr = tid >> 2;           // feature row 0..31
    const int lc = tid & 3;            // 8-float chunk 0..3 within stage
    // two 16B store chunks: c4 = 2*lc, 2*lc+1; swizzled positions
    const uint32_t stoff = lr * 128 + (((2 * lc) ^ (lr & 7)) << 4);

    const float* srcg[GROUP];
    bool validg[GROUP];
#pragma unroll
    for (int g = 0; g < GROUP; ++g) {
        const long b = bbase + g;
        validg[g] = (lr < FEAT) && (b < B);
        srcg[g] = (lr == 0)
            ? dense + b * KDIM + lc * 8
            : sparse + ((b * 26) + (lr - 1)) * (long)KDIM + lc * 8;
    }

    // fragment addressing
    const int q = lane >> 2;           // 0..7
    const int e = lane & 3;            // 0..3
    const uint32_t fbase_off = q * 128 + (e << 2);   // + chunk swizzle later

    float acc[6][4] = {};   // T00a,T00b,T01a,T01b,T11a,T11b
    float4 p0[GROUP], p1[GROUP];

    // ---- prologue: prefetch stage 0 ----
#pragma unroll
    for (int g = 0; g < GROUP; ++g) {
        p0[g] = validg[g] ? *reinterpret_cast<const float4*>(srcg[g])
                          : make_float4(0.f, 0.f, 0.f, 0.f);
        p1[g] = validg[g] ? *reinterpret_cast<const float4*>(srcg[g] + 4)
                          : make_float4(0.f, 0.f, 0.f, 0.f);
    }

#pragma unroll
    for (int s2 = 0; s2 < 4; ++s2) {
        char* bufb = smem + (s2 & 1) * BUF_BYTES;

        // ---- cvt.rna + STS of prefetched stage ----
#pragma unroll
        for (int g = 0; g < GROUP; ++g) {
            uint4 u0, u1;
            u0.x = to_tf32(p0[g].x);  u0.y = to_tf32(p0[g].y);
            u0.z = to_tf32(p0[g].z);  u0.w = to_tf32(p0[g].w);
            u1.x = to_tf32(p1[g].x);  u1.y = to_tf32(p1[g].y);
            u1.z = to_tf32(p1[g].z);  u1.w = to_tf32(p1[g].w);
            char* dst = bufb + g * GRP_BYTES + stoff;
            *reinterpret_cast<uint4*>(dst) = u0;
            *reinterpret_cast<uint4*>(reinterpret_cast<char*>(
                (reinterpret_cast<uintptr_t>(dst)) ^ 16)) = u1;
        }
        __syncthreads();

        // ---- issue prefetch for next stage (hidden under compute) ----
        if (s2 < 3) {
#pragma unroll
            for (int g = 0; g < GROUP; ++g) {
                const float* p = srcg[g] + (s2 + 1) * 32;
                p0[g] = validg[g] ? *reinterpret_cast<const float4*>(p)
                                  : make_float4(0.f, 0.f, 0.f, 0.f);
                p1[g] = validg[g] ? *reinterpret_cast<const float4*>(p + 4)
                                  : make_float4(0.f, 0.f, 0.f, 0.f);
            }
        }

        // ---- compute: 4 k8-steps from buf[s2&1] ----
        const char* wbase = smem + (s2 & 1) * BUF_BYTES + wid * GRP_BYTES;
#pragma unroll
        for (int s = 0; s < 4; ++s) {
            // A tile M=0 (rows 0..15) and M=16 (rows 16..31)
            const uint32_t a0off = fbase_off + ((((2 * s) ^ q) & 7) << 4);
            const char* pa = wbase + a0off;

            uint32_t Ra[4], Rb[4];
            Ra[0] = *reinterpret_cast<const uint32_t*>(pa);
            Ra[1] = *reinterpret_cast<const uint32_t*>(pa + 1024);
            Ra[2] = *reinterpret_cast<const uint32_t*>(
                reinterpret_cast<const char*>(reinterpret_cast<uintptr_t>(pa) ^ 16));
            Ra[3] = *reinterpret_cast<const uint32_t*>(
                reinterpret_cast<const char*>(reinterpret_cast<uintptr_t>(pa + 1024) ^ 16));
            const char* pb = pa + 2048;
            Rb[0] = *reinterpret_cast<const uint32_t*>(pb);
            Rb[1] = *reinterpret_cast<const uint32_t*>(pb + 1024);
            Rb[2] = *reinterpret_cast<const uint32_t*>(
                reinterpret_cast<const char*>(reinterpret_cast<uintptr_t>(pb) ^ 16));
            Rb[3] = *reinterpret_cast<const uint32_t*>(
                reinterpret_cast<const char*>(reinterpret_cast<uintptr_t>(pb + 1024) ^ 16));

            // B fragments are reused A fragments (Gram symmetry):
            // n-tile rows 0-7  -> {Ra0, Ra2};  rows 8-15 -> {Ra1, Ra3}
            // n-tile rows16-23 -> {Rb0, Rb2};  rows24-31 -> {Rb1, Rb3}
            mma_tf32(acc[0], Ra, Ra[0], Ra[2]);
            mma_tf32(acc[1], Ra, Ra[1], Ra[3]);
            mma_tf32(acc[2], Ra, Rb[0], Rb[2]);
            mma_tf32(acc[3], Ra, Rb[1], Rb[3]);
            mma_tf32(acc[4], Rb, Rb[0], Rb[2]);
            mma_tf32(acc[5], Rb, Rb[1], Rb[3]);
        }
        // no trailing barrier: next STS targets the other buffer, whose last
        // readers (compute(s2-1)) finished before this stage's barrier.
    }

    // ---- Stage per-warp triangle into buf0 (compute(3) read only buf1) ----
    {
        float* stg = reinterpret_cast<float*>(smem) + wid * STG_WARP;
        const int r0 = lane >> 2;
        const int c0 = (lane & 3) * 2;
        const int MR[6] = {0, 0, 0, 0, 16, 16};
        const int NC[6] = {0, 8, 16, 24, 16, 24};
#pragma unroll
        for (int t = 0; t < 6; ++t) {
#pragma unroll
            for (int hrow = 0; hrow < 2; ++hrow) {
                const int rr = MR[t] + r0 + hrow * 8;
                const int cc = NC[t] + c0;
                if (rr < FEAT && cc < 28) {
                    stg[rr * STG_STRIDE + cc] = acc[t][hrow * 2];
                    if (cc + 1 < 28)
                        stg[rr * STG_STRIDE + cc + 1] = acc[t][hrow * 2 + 1];
                }
            }
        }
    }
    __syncthreads();

    // ---- Coalesced writeout: contiguous 4*351 floats per CTA ----
    const long obase = bbase * NPAIR;
    const long lim = (long)B * NPAIR;
    const float* stg0 = reinterpret_cast<const float*>(smem);
#pragma unroll
    for (int k = 0; k < 11; ++k) {
        const int idx = k * THREADS + tid;
        if (idx < GROUP * NPAIR && obase + idx < lim) {
            const int g = idx / NPAIR;
            const int ee = idx - g * NPAIR;
            int i = (int)((53.0f - sqrtf(2809.0f - 8.0f * (float)ee)) * 0.5f);
            if (i < 0) i = 0;
            if (i > 25) i = 25;
#pragma unroll
            for (int qq = 0; qq < 2; ++qq) {
                if (i < 25 && ee >= (i + 1) * (52 - i) / 2) ++i;
                if (i > 0 && ee < i * (53 - i) / 2) --i;
            }
            const int j = i + 1 + (ee - i * (53 - i) / 2);
            out[obase + idx] = stg0[g * STG_WARP + i * STG_STRIDE + j];
        }
    }
}

extern "C" void kernel_launch(void* const* d_in, const int* in_sizes, int n_in,
                              void* d_out, int out_size)
{
    const float* dense  = (const float*)d_in[0];   // (B, 128)
    const float* sparse = (const float*)d_in[1];   // (B, 26, 128)
    float* out = (float*)d_out;                    // (B, 351)

    const int B = in_sizes[0] / KDIM;
    const int grid = (B + GROUP - 1) / GROUP;
    interaction_kernel<<<grid, THREADS>>>(dense, sparse, out, B);
}

// round 12
// speedup vs baseline: 1.0424x; 1.0424x over previous
#include <cuda_runtime.h>
#include <cuda_bf16.h>
#include <cstdint>

// InteractionArch via mma.sync bf16 x3 (emulated fp32) with GRAM-SYMMETRY
// FRAGMENT REUSE: for m16n8k16.row.col, the B fragment of C^T equals A
// fragment registers (b0=a0, b1=a2; n-tiles 8..15/16..23/24..31 use the
// a1/a3 and M=16 fragment registers). So the compute phase loads ONLY the
// two A fragments per operand (4 ldmatrix.x4 instead of 8) and issues 18
// HMMA per k16-step with register-sourced B. Halves compute LDSM wavefronts
// and frees ~24 regs -> 5 CTAs/SM (round 10: 128 regs, 4 CTAs, occ 26%).
//
//   D = H*H^T + H*L^T + L*H^T  (fp32 = bf16 hi + lo; L*L^T ~ 2^-16, dropped)
// K = 4 stages of 32, double-buffered smem (2 x 16 KB) + register prefetch
// of stage s+1 issued after the barrier (round-10 pipeline, verified).
//
// Swizzle (64 B bf16 rows, 4 x 16 B chunks): chunk c of row r at position
// c ^ ((r>>1)&3); all STS.128 / ldmatrix octets conflict-free (verified).

#define FEAT 27
#define KDIM 128
#define NPAIR 351
#define GROUP 4
#define THREADS 128
#define BUF_BYTES 16384        // one stage buffer: hi 8 KB + lo 8 KB
#define LO_OFF 8192
#define BATCH_BYTES 2048       // 32 rows x 64 B bf16
#define STG_STRIDE 29
#define STG_WARP 783           // 27 * 29 floats

__device__ __forceinline__ void split2(float x, float y, uint32_t& h, uint32_t& l) {
    asm("cvt.rn.satfinite.bf16x2.f32 %0, %1, %2;" : "=r"(h) : "f"(y), "f"(x));
    float hx = __uint_as_float(h << 16);
    float hy = __uint_as_float(h & 0xffff0000u);
    float lx = x - hx, ly = y - hy;
    asm("cvt.rn.satfinite.bf16x2.f32 %0, %1, %2;" : "=r"(l) : "f"(ly), "f"(lx));
}

__device__ __forceinline__ void ldx4(uint32_t addr, uint32_t* r) {
    asm volatile("ldmatrix.sync.aligned.m8n8.x4.shared.b16 {%0,%1,%2,%3}, [%4];"
                 : "=r"(r[0]), "=r"(r[1]), "=r"(r[2]), "=r"(r[3]) : "r"(addr));
}

__device__ __forceinline__ void mma16816(float* c, const uint32_t* a,
                                         uint32_t b0, uint32_t b1) {
    asm volatile(
        "mma.sync.aligned.m16n8k16.row.col.f32.bf16.bf16.f32 "
        "{%0,%1,%2,%3}, {%4,%5,%6,%7}, {%8,%9}, {%0,%1,%2,%3};"
        : "+f"(c[0]), "+f"(c[1]), "+f"(c[2]), "+f"(c[3])
        : "r"(a[0]), "r"(a[1]), "r"(a[2]), "r"(a[3]), "r"(b0), "r"(b1));
}

__global__ __launch_bounds__(THREADS, 5)
void interaction_kernel(const float* __restrict__ dense,
                        const float* __restrict__ sparse,
                        float* __restrict__ out,
                        int B)
{
    __shared__ __align__(1024) char smem[2 * BUF_BYTES];   // 32 KB

    const int tid = threadIdx.x;
    const int wid = tid >> 5;
    const int lane = tid & 31;
    const long bbase = (long)blockIdx.x * GROUP;

    uint32_t sb;
    asm("{ .reg .u64 t; cvta.to.shared.u64 t, %1; cvt.u32.u64 %0, t; }"
        : "=r"(sb) : "l"((void*)smem));

    // ---- load mapping: quarter-warp per feature-row line (coalesced) ----
    const int lr = tid >> 2;           // feature row 0..31
    const int lc = tid & 3;            // 8-float chunk within stage
    const uint32_t loff = lr * 64 + ((lc ^ ((lr >> 1) & 3)) << 4);

    const float* srcg[GROUP];
    bool validg[GROUP];
#pragma unroll
    for (int g = 0; g < GROUP; ++g) {
        const long b = bbase + g;
        validg[g] = (lr < FEAT) && (b < B);
        srcg[g] = (lr == 0)
            ? dense + b * KDIM + lc * 8
            : sparse + ((b * 26) + (lr - 1)) * (long)KDIM + lc * 8;
    }

    // ldmatrix lane selectors for A fragments (verified rounds 7-10)
    const int arow = lane & 15;
    const int asel = lane >> 4;
    const int aswz = (arow >> 1) & 3;

    float acc[6][4] = {};   // T00a,T00b,T01a,T01b,T11a,T11b
    float4 p0[GROUP], p1[GROUP];

    // ---- prologue: prefetch stage 0 ----
#pragma unroll
    for (int g = 0; g < GROUP; ++g) {
        p0[g] = validg[g] ? *reinterpret_cast<const float4*>(srcg[g])
                          : make_float4(0.f, 0.f, 0.f, 0.f);
        p1[g] = validg[g] ? *reinterpret_cast<const float4*>(srcg[g] + 4)
                          : make_float4(0.f, 0.f, 0.f, 0.f);
    }

#pragma unroll
    for (int s2 = 0; s2 < 4; ++s2) {
        char* bufb = smem + (s2 & 1) * BUF_BYTES;

        // ---- split + STS of prefetched stage ----
#pragma unroll
        for (int g = 0; g < GROUP; ++g) {
            uint4 hi, lo;
            split2(p0[g].x, p0[g].y, hi.x, lo.x);
            split2(p0[g].z, p0[g].w, hi.y, lo.y);
            split2(p1[g].x, p1[g].y, hi.z, lo.z);
            split2(p1[g].z, p1[g].w, hi.w, lo.w);
            const uint32_t off = g * BATCH_BYTES + loff;
            *reinterpret_cast<uint4*>(bufb + off) = hi;
            *reinterpret_cast<uint4*>(bufb + LO_OFF + off) = lo;
        }
        __syncthreads();

        // ---- issue prefetch for next stage (hidden under compute) ----
        if (s2 < 3) {
#pragma unroll
            for (int g = 0; g < GROUP; ++g) {
                const float* p = srcg[g] + (s2 + 1) * 32;
                p0[g] = validg[g] ? *reinterpret_cast<const float4*>(p)
                                  : make_float4(0.f, 0.f, 0.f, 0.f);
                p1[g] = validg[g] ? *reinterpret_cast<const float4*>(p + 4)
                                  : make_float4(0.f, 0.f, 0.f, 0.f);
            }
        }

        // ---- compute: 2 k16-steps, B fragments reused from A registers ----
        const uint32_t hbase = sb + (s2 & 1) * BUF_BYTES + wid * BATCH_BYTES;
        const uint32_t lbase = hbase + LO_OFF;
#pragma unroll
        for (int s = 0; s < 2; ++s) {
            const int ac = 2 * s + asel;

            uint32_t A0h[4], A0l[4], A1h[4], A1l[4];

            const uint32_t offA0 = arow * 64 + ((ac ^ aswz) << 4);
            const uint32_t offA1 = (arow + 16) * 64 + ((ac ^ aswz) << 4);

            ldx4(hbase + offA0, A0h);  ldx4(lbase + offA0, A0l);
            ldx4(hbase + offA1, A1h);  ldx4(lbase + offA1, A1l);

            // n-tiles: 0-7={F[0],F[2]}, 8-15={F[1],F[3]} of the M=0..15 frag;
            //          16-23/24-31 likewise from the M=16..31 frag.
            // H * H^T
            mma16816(acc[0], A0h, A0h[0], A0h[2]);
            mma16816(acc[1], A0h, A0h[1], A0h[3]);
            mma16816(acc[2], A0h, A1h[0], A1h[2]);
            mma16816(acc[3], A0h, A1h[1], A1h[3]);
            mma16816(acc[4], A1h, A1h[0], A1h[2]);
            mma16816(acc[5], A1h, A1h[1], A1h[3]);
            // H * L^T  (B sourced from lo fragments)
            mma16816(acc[0], A0h, A0l[0], A0l[2]);
            mma16816(acc[1], A0h, A0l[1], A0l[3]);
            mma16816(acc[2], A0h, A1l[0], A1l[2]);
            mma16816(acc[3], A0h, A1l[1], A1l[3]);
            mma16816(acc[4], A1h, A1l[0], A1l[2]);
            mma16816(acc[5], A1h, A1l[1], A1l[3]);
            // L * H^T
            mma16816(acc[0], A0l, A0h[0], A0h[2]);
            mma16816(acc[1], A0l, A0h[1], A0h[3]);
            mma16816(acc[2], A0l, A1h[0], A1h[2]);
            mma16816(acc[3], A0l, A1h[1], A1h[3]);
            mma16816(acc[4], A1l, A1h[0], A1h[2]);
            mma16816(acc[5], A1l, A1h[1], A1h[3]);
        }
        // no trailing barrier: next STS targets the other buffer, whose last
        // readers (compute(s2-1)) finished before this stage's barrier.
    }

    // ---- Stage per-warp triangle into buf0 (compute(3) read only buf1) ----
    {
        float* stg = reinterpret_cast<float*>(smem) + wid * STG_WARP;
        const int r0 = lane >> 2;
        const int c0 = (lane & 3) * 2;
        const int MR[6] = {0, 0, 0, 0, 16, 16};
        const int NC[6] = {0, 8, 16, 24, 16, 24};
#pragma unroll
        for (int t = 0; t < 6; ++t) {
#pragma unroll
            for (int hrow = 0; hrow < 2; ++hrow) {
                const int rr = MR[t] + r0 + hrow * 8;
                const int cc = NC[t] + c0;
                if (rr < FEAT && cc < 28) {
                    stg[rr * STG_STRIDE + cc] = acc[t][hrow * 2];
                    if (cc + 1 < 28)
                        stg[rr * STG_STRIDE + cc + 1] = acc[t][hrow * 2 + 1];
                }
            }
        }
    }
    __syncthreads();

    // ---- Coalesced writeout: contiguous 4*351 floats per CTA ----
    const long obase = bbase * NPAIR;
    const long lim = (long)B * NPAIR;
    const float* stg0 = reinterpret_cast<const float*>(smem);
#pragma unroll
    for (int k = 0; k < 11; ++k) {
        const int idx = k * THREADS + tid;
        if (idx < GROUP * NPAIR && obase + idx < lim) {
            const int g = idx / NPAIR;
            const int e = idx - g * NPAIR;
            int i = (int)((53.0f - sqrtf(2809.0f - 8.0f * (float)e)) * 0.5f);
            if (i < 0) i = 0;
            if (i > 25) i = 25;
#pragma unroll
            for (int q = 0; q < 2; ++q) {
                if (i < 25 && e >= (i + 1) * (52 - i) / 2) ++i;
                if (i > 0 && e < i * (53 - i) / 2) --i;
            }
            const int j = i + 1 + (e - i * (53 - i) / 2);
            out[obase + idx] = stg0[g * STG_WARP + i * STG_STRIDE + j];
        }
    }
}

extern "C" void kernel_launch(void* const* d_in, const int* in_sizes, int n_in,
                              void* d_out, int out_size)
{
    const float* dense  = (const float*)d_in[0];   // (B, 128)
    const float* sparse = (const float*)d_in[1];   // (B, 26, 128)
    float* out = (float*)d_out;                    // (B, 351)

    const int B = in_sizes[0] / KDIM;
    const int grid = (B + GROUP - 1) / GROUP;
    interaction_kernel<<<grid, THREADS>>>(dense, sparse, out, B);
}

// round 13
// speedup vs baseline: 1.4093x; 1.3519x over previous
#include <cuda_runtime.h>
#include <cuda_bf16.h>
#include <cstdint>

// InteractionArch via mma.sync bf16 x3 (emulated fp32) with Gram-symmetry
// fragment reuse (B fragments == A fragment registers for m16n8k16.row.col
// when both operands are the same matrix; validated bit-exact in round 12).
//
// Round 13 = round 12 WITHOUT the __launch_bounds__ min-blocks clamp (it
// forced 96 regs and spilled: issue 60%, alu 46%, dur regressed) and with
// register trims: per-thread fixed feature row means the 4 per-group source
// pointers collapse to one base + one stride.
//
//   D = H*H^T + H*L^T + L*H^T  (fp32 = bf16 hi + lo; L*L^T ~ 2^-16, dropped)
// K = 4 stages of 32, double-buffered smem (2 x 16 KB) + register prefetch
// of stage s+1 issued after the barrier (round-10 pipeline, verified).
// 18 HMMA per k16-step; only 4 ldmatrix.x4 per k-step (A hi/lo, M=0 and
// M=16); B operands sourced from those same registers.
//
// Swizzle (64 B bf16 rows, 4 x 16 B chunks): chunk c of row r at position
// c ^ ((r>>1)&3); all STS.128 / ldmatrix octets conflict-free (verified).

#define FEAT 27
#define KDIM 128
#define NPAIR 351
#define GROUP 4
#define THREADS 128
#define BUF_BYTES 16384        // one stage buffer: hi 8 KB + lo 8 KB
#define LO_OFF 8192
#define BATCH_BYTES 2048       // 32 rows x 64 B bf16
#define STG_STRIDE 29
#define STG_WARP 783           // 27 * 29 floats

__device__ __forceinline__ void split2(float x, float y, uint32_t& h, uint32_t& l) {
    asm("cvt.rn.satfinite.bf16x2.f32 %0, %1, %2;" : "=r"(h) : "f"(y), "f"(x));
    float hx = __uint_as_float(h << 16);
    float hy = __uint_as_float(h & 0xffff0000u);
    float lx = x - hx, ly = y - hy;
    asm("cvt.rn.satfinite.bf16x2.f32 %0, %1, %2;" : "=r"(l) : "f"(ly), "f"(lx));
}

__device__ __forceinline__ void ldx4(uint32_t addr, uint32_t* r) {
    asm volatile("ldmatrix.sync.aligned.m8n8.x4.shared.b16 {%0,%1,%2,%3}, [%4];"
                 : "=r"(r[0]), "=r"(r[1]), "=r"(r[2]), "=r"(r[3]) : "r"(addr));
}

__device__ __forceinline__ void mma16816(float* c, const uint32_t* a,
                                         uint32_t b0, uint32_t b1) {
    asm volatile(
        "mma.sync.aligned.m16n8k16.row.col.f32.bf16.bf16.f32 "
        "{%0,%1,%2,%3}, {%4,%5,%6,%7}, {%8,%9}, {%0,%1,%2,%3};"
        : "+f"(c[0]), "+f"(c[1]), "+f"(c[2]), "+f"(c[3])
        : "r"(a[0]), "r"(a[1]), "r"(a[2]), "r"(a[3]), "r"(b0), "r"(b1));
}

__global__ __launch_bounds__(THREADS)
void interaction_kernel(const float* __restrict__ dense,
                        const float* __restrict__ sparse,
                        float* __restrict__ out,
                        int B)
{
    __shared__ __align__(1024) char smem[2 * BUF_BYTES];   // 32 KB

    const int tid = threadIdx.x;
    const int wid = tid >> 5;
    const int lane = tid & 31;
    const long bbase = (long)blockIdx.x * GROUP;

    uint32_t sb;
    asm("{ .reg .u64 t; cvta.to.shared.u64 t, %1; cvt.u32.u64 %0, t; }"
        : "=r"(sb) : "l"((void*)smem));

    // ---- load mapping: quarter-warp per feature-row line (coalesced) ----
    const int lr = tid >> 2;           // feature row 0..31 (fixed per thread)
    const int lc = tid & 3;            // 8-float chunk within stage
    const uint32_t loff = lr * 64 + ((lc ^ ((lr >> 1) & 3)) << 4);

    // single base pointer + per-group stride (row lr fixed => same array)
    const float* srcbase = (lr == 0)
        ? dense + bbase * KDIM + lc * 8
        : sparse + ((bbase * 26) + (lr - 1)) * (long)KDIM + lc * 8;
    const long gstride = (lr == 0) ? (long)KDIM : (long)26 * KDIM;
    const bool rowok = (lr < FEAT);

    // ldmatrix lane selectors for A fragments (verified rounds 7-12)
    const int arow = lane & 15;
    const int asel = lane >> 4;
    const int aswz = (arow >> 1) & 3;

    float acc[6][4] = {};   // T00a,T00b,T01a,T01b,T11a,T11b
    float4 p0[GROUP], p1[GROUP];

    // ---- prologue: prefetch stage 0 ----
#pragma unroll
    for (int g = 0; g < GROUP; ++g) {
        const bool v = rowok && (bbase + g < B);
        const float* p = srcbase + g * gstride;
        p0[g] = v ? *reinterpret_cast<const float4*>(p)
                  : make_float4(0.f, 0.f, 0.f, 0.f);
        p1[g] = v ? *reinterpret_cast<const float4*>(p + 4)
                  : make_float4(0.f, 0.f, 0.f, 0.f);
    }

#pragma unroll
    for (int s2 = 0; s2 < 4; ++s2) {
        char* bufb = smem + (s2 & 1) * BUF_BYTES;

        // ---- split + STS of prefetched stage ----
#pragma unroll
        for (int g = 0; g < GROUP; ++g) {
            uint4 hi, lo;
            split2(p0[g].x, p0[g].y, hi.x, lo.x);
            split2(p0[g].z, p0[g].w, hi.y, lo.y);
            split2(p1[g].x, p1[g].y, hi.z, lo.z);
            split2(p1[g].z, p1[g].w, hi.w, lo.w);
            const uint32_t off = g * BATCH_BYTES + loff;
            *reinterpret_cast<uint4*>(bufb + off) = hi;
            *reinterpret_cast<uint4*>(bufb + LO_OFF + off) = lo;
        }
        __syncthreads();

        // ---- issue prefetch for next stage (hidden under compute) ----
        if (s2 < 3) {
#pragma unroll
            for (int g = 0; g < GROUP; ++g) {
                const bool v = rowok && (bbase + g < B);
                const float* p = srcbase + g * gstride + (s2 + 1) * 32;
                p0[g] = v ? *reinterpret_cast<const float4*>(p)
                          : make_float4(0.f, 0.f, 0.f, 0.f);
                p1[g] = v ? *reinterpret_cast<const float4*>(p + 4)
                          : make_float4(0.f, 0.f, 0.f, 0.f);
            }
        }

        // ---- compute: 2 k16-steps, B fragments reused from A registers ----
        const uint32_t hbase = sb + (s2 & 1) * BUF_BYTES + wid * BATCH_BYTES;
        const uint32_t lbase = hbase + LO_OFF;
#pragma unroll
        for (int s = 0; s < 2; ++s) {
            const int ac = 2 * s + asel;

            uint32_t A0h[4], A0l[4], A1h[4], A1l[4];

            const uint32_t offA0 = arow * 64 + ((ac ^ aswz) << 4);
            const uint32_t offA1 = (arow + 16) * 64 + ((ac ^ aswz) << 4);

            ldx4(hbase + offA0, A0h);  ldx4(lbase + offA0, A0l);
            ldx4(hbase + offA1, A1h);  ldx4(lbase + offA1, A1l);

            // n-tiles: 0-7={F[0],F[2]}, 8-15={F[1],F[3]} of the M=0..15 frag;
            //          16-23/24-31 likewise from the M=16..31 frag.
            // H * H^T
            mma16816(acc[0], A0h, A0h[0], A0h[2]);
            mma16816(acc[1], A0h, A0h[1], A0h[3]);
            mma16816(acc[2], A0h, A1h[0], A1h[2]);
            mma16816(acc[3], A0h, A1h[1], A1h[3]);
            mma16816(acc[4], A1h, A1h[0], A1h[2]);
            mma16816(acc[5], A1h, A1h[1], A1h[3]);
            // H * L^T  (B sourced from lo fragments)
            mma16816(acc[0], A0h, A0l[0], A0l[2]);
            mma16816(acc[1], A0h, A0l[1], A0l[3]);
            mma16816(acc[2], A0h, A1l[0], A1l[2]);
            mma16816(acc[3], A0h, A1l[1], A1l[3]);
            mma16816(acc[4], A1h, A1l[0], A1l[2]);
            mma16816(acc[5], A1h, A1l[1], A1l[3]);
            // L * H^T
            mma16816(acc[0], A0l, A0h[0], A0h[2]);
            mma16816(acc[1], A0l, A0h[1], A0h[3]);
            mma16816(acc[2], A0l, A1h[0], A1h[2]);
            mma16816(acc[3], A0l, A1h[1], A1h[3]);
            mma16816(acc[4], A1l, A1h[0], A1h[2]);
            mma16816(acc[5], A1l, A1h[1], A1h[3]);
        }
        // no trailing barrier: next STS targets the other buffer, whose last
        // readers (compute(s2-1)) finished before this stage's barrier.
    }

    // ---- Stage per-warp triangle into buf0 (compute(3) read only buf1) ----
    {
        float* stg = reinterpret_cast<float*>(smem) + wid * STG_WARP;
        const int r0 = lane >> 2;
        const int c0 = (lane & 3) * 2;
        const int MR[6] = {0, 0, 0, 0, 16, 16};
        const int NC[6] = {0, 8, 16, 24, 16, 24};
#pragma unroll
        for (int t = 0; t < 6; ++t) {
#pragma unroll
            for (int hrow = 0; hrow < 2; ++hrow) {
                const int rr = MR[t] + r0 + hrow * 8;
                const int cc = NC[t] + c0;
                if (rr < FEAT && cc < 28) {
                    stg[rr * STG_STRIDE + cc] = acc[t][hrow * 2];
                    if (cc + 1 < 28)
                        stg[rr * STG_STRIDE + cc + 1] = acc[t][hrow * 2 + 1];
                }
            }
        }
    }
    __syncthreads();

    // ---- Coalesced writeout: contiguous 4*351 floats per CTA ----
    const long obase = bbase * NPAIR;
    const long lim = (long)B * NPAIR;
    const float* stg0 = reinterpret_cast<const float*>(smem);
#pragma unroll
    for (int k = 0; k < 11; ++k) {
        const int idx = k * THREADS + tid;
        if (idx < GROUP * NPAIR && obase + idx < lim) {
            const int g = idx / NPAIR;
            const int e = idx - g * NPAIR;
            int i = (int)((53.0f - sqrtf(2809.0f - 8.0f * (float)e)) * 0.5f);
            if (i < 0) i = 0;
            if (i > 25) i = 25;
#pragma unroll
            for (int q = 0; q < 2; ++q) {
                if (i < 25 && e >= (i + 1) * (52 - i) / 2) ++i;
                if (i > 0 && e < i * (53 - i) / 2) --i;
            }
            const int j = i + 1 + (e - i * (53 - i) / 2);
            out[obase + idx] = stg0[g * STG_WARP + i * STG_STRIDE + j];
        }
    }
}

extern "C" void kernel_launch(void* const* d_in, const int* in_sizes, int n_in,
                              void* d_out, int out_size)
{
    const float* dense  = (const float*)d_in[0];   // (B, 128)
    const float* sparse = (const float*)d_in[1];   // (B, 26, 128)
    float* out = (float*)d_out;                    // (B, 351)

    const int B = in_sizes[0] / KDIM;
    const int grid = (B + GROUP - 1) / GROUP;
    interaction_kernel<<<grid, THREADS>>>(dense, sparse, out, B);
}

// round 14
// speedup vs baseline: 1.4943x; 1.0603x over previous
#include <cuda_runtime.h>
#include <cuda_bf16.h>
#include <cstdint>

// InteractionArch via mma.sync bf16 x3 (emulated fp32) with Gram-symmetry
// fragment reuse (B fragments == A fragment registers for m16n8k16.row.col;
// validated bit-exact in rounds 12-13).
//
// Round 14 = round 13 (215.5 us, regs 80, no spill) plus:
//  - epilogue LUT: triangle index e -> staging address via a 351-entry
//    uint16 smem table built in 6 integer-only iterations at kernel start
//    (overlapped with prologue LDG latency); kills the sqrt+fixup chain
//    that made alu 41% of peak.
//  - stage-(s+1) prefetch LDGs issued BEFORE the barrier (they only WAR
//    p0/p1 after their last read), hiding LDG latency under barrier wait
//    plus compute.
//
//   D = H*H^T + H*L^T + L*H^T  (fp32 = bf16 hi + lo; L*L^T ~ 2^-16, dropped)
// K = 4 stages of 32, double-buffered smem (2 x 16 KB) + register prefetch.
// 18 HMMA per k16-step; 4 ldmatrix.x4 per k-step; B sourced from A regs.
//
// Swizzle (64 B bf16 rows, 4 x 16 B chunks): chunk c of row r at position
// c ^ ((r>>1)&3); all STS.128 / ldmatrix octets conflict-free (verified).

#define FEAT 27
#define KDIM 128
#define NPAIR 351
#define GROUP 4
#define THREADS 128
#define BUF_BYTES 16384        // one stage buffer: hi 8 KB + lo 8 KB
#define LO_OFF 8192
#define BATCH_BYTES 2048       // 32 rows x 64 B bf16
#define STG_STRIDE 29
#define STG_WARP 783           // 27 * 29 floats
#define LUT_OFF (2 * BUF_BYTES)

__device__ __forceinline__ void split2(float x, float y, uint32_t& h, uint32_t& l) {
    asm("cvt.rn.satfinite.bf16x2.f32 %0, %1, %2;" : "=r"(h) : "f"(y), "f"(x));
    float hx = __uint_as_float(h << 16);
    float hy = __uint_as_float(h & 0xffff0000u);
    float lx = x - hx, ly = y - hy;
    asm("cvt.rn.satfinite.bf16x2.f32 %0, %1, %2;" : "=r"(l) : "f"(ly), "f"(lx));
}

__device__ __forceinline__ void ldx4(uint32_t addr, uint32_t* r) {
    asm volatile("ldmatrix.sync.aligned.m8n8.x4.shared.b16 {%0,%1,%2,%3}, [%4];"
                 : "=r"(r[0]), "=r"(r[1]), "=r"(r[2]), "=r"(r[3]) : "r"(addr));
}

__device__ __forceinline__ void mma16816(float* c, const uint32_t* a,
                                         uint32_t b0, uint32_t b1) {
    asm volatile(
        "mma.sync.aligned.m16n8k16.row.col.f32.bf16.bf16.f32 "
        "{%0,%1,%2,%3}, {%4,%5,%6,%7}, {%8,%9}, {%0,%1,%2,%3};"
        : "+f"(c[0]), "+f"(c[1]), "+f"(c[2]), "+f"(c[3])
        : "r"(a[0]), "r"(a[1]), "r"(a[2]), "r"(a[3]), "r"(b0), "r"(b1));
}

__global__ __launch_bounds__(THREADS)
void interaction_kernel(const float* __restrict__ dense,
                        const float* __restrict__ sparse,
                        float* __restrict__ out,
                        int B)
{
    __shared__ __align__(1024) char smem[2 * BUF_BYTES + 1024];   // +LUT

    const int tid = threadIdx.x;
    const int wid = tid >> 5;
    const int lane = tid & 31;
    const long bbase = (long)blockIdx.x * GROUP;

    uint32_t sb;
    asm("{ .reg .u64 t; cvta.to.shared.u64 t, %1; cvt.u32.u64 %0, t; }"
        : "=r"(sb) : "l"((void*)smem));

    // ---- load mapping: quarter-warp per feature-row line (coalesced) ----
    const int lr = tid >> 2;           // feature row 0..31 (fixed per thread)
    const int lc = tid & 3;            // 8-float chunk within stage
    const uint32_t loff = lr * 64 + ((lc ^ ((lr >> 1) & 3)) << 4);

    // single base pointer + per-group stride (row lr fixed => same array)
    const float* srcbase = (lr == 0)
        ? dense + bbase * KDIM + lc * 8
        : sparse + ((bbase * 26) + (lr - 1)) * (long)KDIM + lc * 8;
    const long gstride = (lr == 0) ? (long)KDIM : (long)26 * KDIM;
    const bool rowok = (lr < FEAT);
    bool vg[GROUP];
#pragma unroll
    for (int g = 0; g < GROUP; ++g) vg[g] = rowok && (bbase + g < B);

    // ldmatrix lane selectors for A fragments (verified rounds 7-13)
    const int arow = lane & 15;
    const int asel = lane >> 4;
    const int aswz = (arow >> 1) & 3;

    float acc[6][4] = {};   // T00a,T00b,T01a,T01b,T11a,T11b
    float4 p0[GROUP], p1[GROUP];

    // ---- prologue: prefetch stage 0 (issue before LUT build) ----
#pragma unroll
    for (int g = 0; g < GROUP; ++g) {
        const float* p = srcbase + g * gstride;
        p0[g] = vg[g] ? *reinterpret_cast<const float4*>(p)
                      : make_float4(0.f, 0.f, 0.f, 0.f);
        p1[g] = vg[g] ? *reinterpret_cast<const float4*>(p + 4)
                      : make_float4(0.f, 0.f, 0.f, 0.f);
    }

    // ---- build epilogue LUT: e -> i*STG_STRIDE + j (integer-only) ----
    {
        uint16_t* lutw = reinterpret_cast<uint16_t*>(smem + LUT_OFF);
#pragma unroll
        for (int t = 0; t < 6; ++t) {
            const int id = t * THREADS + tid;
            if (id < FEAT * FEAT) {
                const int i = id / FEAT;
                const int j = id - i * FEAT;
                if (j > i) {
                    const int e = i * (2 * FEAT - i - 1) / 2 + (j - i - 1);
                    lutw[e] = (uint16_t)(i * STG_STRIDE + j);
                }
            }
        }
    }

#pragma unroll
    for (int s2 = 0; s2 < 4; ++s2) {
        char* bufb = smem + (s2 & 1) * BUF_BYTES;

        // ---- split + STS of prefetched stage ----
#pragma unroll
        for (int g = 0; g < GROUP; ++g) {
            uint4 hi, lo;
            split2(p0[g].x, p0[g].y, hi.x, lo.x);
            split2(p0[g].z, p0[g].w, hi.y, lo.y);
            split2(p1[g].x, p1[g].y, hi.z, lo.z);
            split2(p1[g].z, p1[g].w, hi.w, lo.w);
            const uint32_t off = g * BATCH_BYTES + loff;
            *reinterpret_cast<uint4*>(bufb + off) = hi;
            *reinterpret_cast<uint4*>(bufb + LO_OFF + off) = lo;
        }

        // ---- prefetch next stage BEFORE the barrier (WAR on p0/p1 only) ----
        if (s2 < 3) {
#pragma unroll
            for (int g = 0; g < GROUP; ++g) {
                const float* p = srcbase + g * gstride + (s2 + 1) * 32;
                p0[g] = vg[g] ? *reinterpret_cast<const float4*>(p)
                              : make_float4(0.f, 0.f, 0.f, 0.f);
                p1[g] = vg[g] ? *reinterpret_cast<const float4*>(p + 4)
                              : make_float4(0.f, 0.f, 0.f, 0.f);
            }
        }
        __syncthreads();

        // ---- compute: 2 k16-steps, B fragments reused from A registers ----
        const uint32_t hbase = sb + (s2 & 1) * BUF_BYTES + wid * BATCH_BYTES;
        const uint32_t lbase = hbase + LO_OFF;
#pragma unroll
        for (int s = 0; s < 2; ++s) {
            const int ac = 2 * s + asel;

            uint32_t A0h[4], A0l[4], A1h[4], A1l[4];

            const uint32_t offA0 = arow * 64 + ((ac ^ aswz) << 4);
            const uint32_t offA1 = (arow + 16) * 64 + ((ac ^ aswz) << 4);

            ldx4(hbase + offA0, A0h);  ldx4(lbase + offA0, A0l);
            ldx4(hbase + offA1, A1h);  ldx4(lbase + offA1, A1l);

            // n-tiles: 0-7={F[0],F[2]}, 8-15={F[1],F[3]} of the M=0..15 frag;
            //          16-23/24-31 likewise from the M=16..31 frag.
            // H * H^T
            mma16816(acc[0], A0h, A0h[0], A0h[2]);
            mma16816(acc[1], A0h, A0h[1], A0h[3]);
            mma16816(acc[2], A0h, A1h[0], A1h[2]);
            mma16816(acc[3], A0h, A1h[1], A1h[3]);
            mma16816(acc[4], A1h, A1h[0], A1h[2]);
            mma16816(acc[5], A1h, A1h[1], A1h[3]);
            // H * L^T  (B sourced from lo fragments)
            mma16816(acc[0], A0h, A0l[0], A0l[2]);
            mma16816(acc[1], A0h, A0l[1], A0l[3]);
            mma16816(acc[2], A0h, A1l[0], A1l[2]);
            mma16816(acc[3], A0h, A1l[1], A1l[3]);
            mma16816(acc[4], A1h, A1l[0], A1l[2]);
            mma16816(acc[5], A1h, A1l[1], A1l[3]);
            // L * H^T
            mma16816(acc[0], A0l, A0h[0], A0h[2]);
            mma16816(acc[1], A0l, A0h[1], A0h[3]);
            mma16816(acc[2], A0l, A1h[0], A1h[2]);
            mma16816(acc[3], A0l, A1h[1], A1h[3]);
            mma16816(acc[4], A1l, A1h[0], A1h[2]);
            mma16816(acc[5], A1l, A1h[1], A1h[3]);
        }
        // no trailing barrier: next STS targets the other buffer, whose last
        // readers (compute(s2-1)) finished before this stage's barrier.
    }

    // ---- Stage per-warp triangle into buf0 (compute(3) read only buf1) ----
    {
        float* stg = reinterpret_cast<float*>(smem) + wid * STG_WARP;
        const int r0 = lane >> 2;
        const int c0 = (lane & 3) * 2;
        const int MR[6] = {0, 0, 0, 0, 16, 16};
        const int NC[6] = {0, 8, 16, 24, 16, 24};
#pragma unroll
        for (int t = 0; t < 6; ++t) {
#pragma unroll
            for (int hrow = 0; hrow < 2; ++hrow) {
                const int rr = MR[t] + r0 + hrow * 8;
                const int cc = NC[t] + c0;
                if (rr < FEAT && cc < 28) {
                    stg[rr * STG_STRIDE + cc] = acc[t][hrow * 2];
                    if (cc + 1 < 28)
                        stg[rr * STG_STRIDE + cc + 1] = acc[t][hrow * 2 + 1];
                }
            }
        }
    }
    __syncthreads();

    // ---- Coalesced writeout via LUT: contiguous 4*351 floats per CTA ----
    const long obase = bbase * NPAIR;
    const long lim = (long)B * NPAIR;
    const float* stg0 = reinterpret_cast<const float*>(smem);
    const uint16_t* lut = reinterpret_cast<const uint16_t*>(smem + LUT_OFF);
#pragma unroll
    for (int k = 0; k < 11; ++k) {
        const int idx = k * THREADS + tid;
        if (idx < GROUP * NPAIR && obase + idx < lim) {
            const int g = (idx >= NPAIR) + (idx >= 2 * NPAIR) + (idx >= 3 * NPAIR);
            const int e = idx - g * NPAIR;
            out[obase + idx] = stg0[g * STG_WARP + lut[e]];
        }
    }
}

extern "C" void kernel_launch(void* const* d_in, const int* in_sizes, int n_in,
                              void* d_out, int out_size)
{
    const float* dense  = (const float*)d_in[0];   // (B, 128)
    const float* sparse = (const float*)d_in[1];   // (B, 26, 128)
    float* out = (float*)d_out;                    // (B, 351)

    const int B = in_sizes[0] / KDIM;
    const int grid = (B + GROUP - 1) / GROUP;
    interaction_kernel<<<grid, THREADS>>>(dense, sparse, out, B);
}